// round 16
// baseline (speedup 1.0000x reference)
#include <cuda_runtime.h>
#include <cuda_bf16.h>
#include <math.h>
#include <stdint.h>

#define NN 100000
#define NE 320000
#define NG 512
#define FDIM 256
#define FOUT 128
#define NBLK 391   // ceil(NN/256)

// ---------------- scratch (static device memory; no allocation) ----------------
__device__ __align__(16) float g_bufH[(size_t)NN * FDIM];
__device__ __align__(16) __nv_bfloat16 g_ahi[(size_t)(NN + 128) * FDIM];
__device__ __align__(16) __nv_bfloat16 g_alo[(size_t)(NN + 128) * FDIM];
__device__ __align__(16) __nv_bfloat16 g_xhi[(size_t)(NN + 128) * 128];
__device__ __align__(16) __nv_bfloat16 g_xlo[(size_t)(NN + 128) * 128];
__device__ float g_dinv[NN];
__device__ int   g_deg[NN];
__device__ int   g_rowptr[NN];
__device__ int   g_cursor[NN];
__device__ int   g_state[NBLK];
__device__ int   g_csrc[NE];
__device__ float g_cnrm[NE];
__device__ int   g_src[NE];
__device__ int   g_dst[NE];
__device__ int   g_batch[NN];
__device__ __align__(16) __nv_bfloat16 g_w1hi[128 * 256];
__device__ __align__(16) __nv_bfloat16 g_w1lo[128 * 256];
__device__ __align__(16) __nv_bfloat16 g_w2hi[256 * 256];
__device__ __align__(16) __nv_bfloat16 g_w2lo[256 * 256];
__device__ __align__(16) __nv_bfloat16 g_w3hi[256 * 256];
__device__ __align__(16) __nv_bfloat16 g_w3lo[256 * 256];

// ---------------- helpers ----------------
__device__ __forceinline__ uint32_t smem_u32(const void* p) {
    uint32_t a;
    asm("{ .reg .u64 t; cvta.to.shared.u64 t, %1; cvt.u32.u64 %0, t; }" : "=r"(a) : "l"(p));
    return a;
}
__device__ __forceinline__ void ldmat_x4(uint32_t* r, uint32_t addr) {
    asm volatile("ldmatrix.sync.aligned.m8n8.x4.shared.b16 {%0,%1,%2,%3}, [%4];"
                 : "=r"(r[0]), "=r"(r[1]), "=r"(r[2]), "=r"(r[3]) : "r"(addr));
}
__device__ __forceinline__ void mma16816(float* c, const uint32_t* a, const uint32_t* b) {
    asm volatile("mma.sync.aligned.m16n8k16.row.col.f32.bf16.bf16.f32 "
                 "{%0,%1,%2,%3}, {%4,%5,%6,%7}, {%8,%9}, {%0,%1,%2,%3};"
                 : "+f"(c[0]), "+f"(c[1]), "+f"(c[2]), "+f"(c[3])
                 : "r"(a[0]), "r"(a[1]), "r"(a[2]), "r"(a[3]), "r"(b[0]), "r"(b[1]));
}
__device__ __forceinline__ void cp16(uint32_t smem_addr, const void* gptr) {
    asm volatile("cp.async.cg.shared.global [%0], [%1], 16;" :: "r"(smem_addr), "l"(gptr));
}
#define CP_COMMIT() asm volatile("cp.async.commit_group;" ::: "memory")
#define CP_WAIT(n)  asm volatile("cp.async.wait_group %0;" :: "n"(n) : "memory")

__device__ __forceinline__ void gdc_wait()   { asm volatile("griddepcontrol.wait;" ::: "memory"); }
__device__ __forceinline__ void gdc_launch() { asm volatile("griddepcontrol.launch_dependents;" ::: "memory"); }

__device__ __forceinline__ void split4(float4 v, uint2& hp, uint2& lp) {
    __nv_bfloat16 h0 = __float2bfloat16(v.x), h1 = __float2bfloat16(v.y);
    __nv_bfloat16 h2 = __float2bfloat16(v.z), h3 = __float2bfloat16(v.w);
    __nv_bfloat16 l0 = __float2bfloat16(v.x - __bfloat162float(h0));
    __nv_bfloat16 l1 = __float2bfloat16(v.y - __bfloat162float(h1));
    __nv_bfloat16 l2 = __float2bfloat16(v.z - __bfloat162float(h2));
    __nv_bfloat16 l3 = __float2bfloat16(v.w - __bfloat162float(h3));
    hp.x = ((uint32_t)__bfloat16_as_ushort(h1) << 16) | __bfloat16_as_ushort(h0);
    hp.y = ((uint32_t)__bfloat16_as_ushort(h3) << 16) | __bfloat16_as_ushort(h2);
    lp.x = ((uint32_t)__bfloat16_as_ushort(l1) << 16) | __bfloat16_as_ushort(l0);
    lp.y = ((uint32_t)__bfloat16_as_ushort(l3) << 16) | __bfloat16_as_ushort(l2);
}
__device__ __forceinline__ void split2(float a, float b, uint32_t& hp, uint32_t& lp) {
    __nv_bfloat16 h0 = __float2bfloat16(a), h1 = __float2bfloat16(b);
    __nv_bfloat16 l0 = __float2bfloat16(a - __bfloat162float(h0));
    __nv_bfloat16 l1 = __float2bfloat16(b - __bfloat162float(h1));
    hp = ((uint32_t)__bfloat16_as_ushort(h1) << 16) | __bfloat16_as_ushort(h0);
    lp = ((uint32_t)__bfloat16_as_ushort(l1) << 16) | __bfloat16_as_ushort(l0);
}

// ---------------- zero ----------------
__global__ void k_zero() {
    int i = blockIdx.x * blockDim.x + threadIdx.x;
    if (i < NN) g_deg[i] = 0;
    if (i < NBLK) g_state[i] = 0;
}

// ---------------- merged prep (edges + batch + weight splits) ----------
#define PW1 (128 * 256)
#define PW2 (256 * 256)
#define P_TOTAL (PW1 + 2 * PW2 + NE + NN)

__global__ void k_prep(const void* e, const void* b,
                       const float* __restrict__ W1,
                       const float* __restrict__ W2, const float* __restrict__ W3) {
    __shared__ int s64;
    if (threadIdx.x == 0) {
        const long long* p = (const long long*)e;
        int is64 = 1;
        for (int t = 0; t < 16; t++) {
            long long v = p[t];
            if (v < 0 || v >= NN) is64 = 0;
        }
        s64 = is64;
    }
    __syncthreads();
    int f64 = s64;
    int i = blockIdx.x * blockDim.x + threadIdx.x;
    if (i < PW1) {
        int k = i >> 8, n = i & 255;
        float v = W1[i];
        __nv_bfloat16 h = __float2bfloat16(v);
        g_w1hi[(size_t)n * 128 + k] = h;
        g_w1lo[(size_t)n * 128 + k] = __float2bfloat16(v - __bfloat162float(h));
        return;
    }
    i -= PW1;
    if (i < PW2) {
        int k = i >> 8, n = i & 255;
        float v = W2[i];
        __nv_bfloat16 h = __float2bfloat16(v);
        g_w2hi[(size_t)n * 256 + k] = h;
        g_w2lo[(size_t)n * 256 + k] = __float2bfloat16(v - __bfloat162float(h));
        return;
    }
    i -= PW2;
    if (i < PW2) {
        int k = i >> 8, n = i & 255;
        float v = W3[i];
        __nv_bfloat16 h = __float2bfloat16(v);
        g_w3hi[(size_t)n * 256 + k] = h;
        g_w3lo[(size_t)n * 256 + k] = __float2bfloat16(v - __bfloat162float(h));
        return;
    }
    i -= PW2;
    if (i < NE) {
        int s, d;
        if (f64) {
            const long long* p = (const long long*)e;
            s = (int)p[i]; d = (int)p[NE + i];
        } else {
            const int* p = (const int*)e;
            s = p[i]; d = p[NE + i];
        }
        g_src[i] = s;
        g_dst[i] = d;
        atomicAdd(&g_deg[d], 1);
        return;
    }
    i -= NE;
    if (i < NN) {
        if (f64) g_batch[i] = (int)((const long long*)b)[i];
        else     g_batch[i] = ((const int*)b)[i];
    }
}

// ---------------- decoupled-lookback scan ----------------
__global__ void k_scan() {
    __shared__ int s[256];
    __shared__ int sprefix;
    int tid = threadIdx.x;
    int blk = blockIdx.x;
    int i = blk * 256 + tid;
    int deg = (i < NN) ? g_deg[i] : 0;
    s[tid] = deg;
#pragma unroll
    for (int off = 1; off < 256; off <<= 1) {
        __syncthreads();
        int t = (tid >= off) ? s[tid - off] : 0;
        __syncthreads();
        s[tid] += t;
    }
    __syncthreads();
    int total = s[255];
    if (tid == 0) {
        if (blk == 0) {
            atomicExch(&g_state[0], (2 << 28) | total);
            sprefix = 0;
        } else {
            atomicExch(&g_state[blk], (1 << 28) | total);
            int run = 0, j = blk - 1;
            while (true) {
                int w = atomicAdd(&g_state[j], 0);
                int f = w >> 28;
                if (f == 0) continue;
                run += (w & 0x0FFFFFFF);
                if (f == 2) break;
                j--;
            }
            atomicExch(&g_state[blk], (2 << 28) | (run + total));
            sprefix = run;
        }
    }
    __syncthreads();
    if (i < NN) {
        g_rowptr[i] = sprefix + s[tid] - deg;
        g_cursor[i] = 0;
        g_dinv[i] = rsqrtf((float)deg + 1.0f);
    }
}

__global__ void k_csrfill() {
    int e = blockIdx.x * blockDim.x + threadIdx.x;
    if (e >= NE) return;
    int s = g_src[e], d = g_dst[e];
    int pos = atomicAdd(&g_cursor[d], 1);
    int slot = g_rowptr[d] + pos;
    g_csrc[slot] = s;
    g_cnrm[slot] = g_dinv[s] * g_dinv[d];
}

// ---------------- layer-1 pre-aggregation: xagg = A_norm @ x (128-dim) ----------
__global__ void __launch_bounds__(256) k_gatherx(const float* __restrict__ x) {
    int node = blockIdx.x * 8 + (threadIdx.x >> 5);
    int lane = threadIdx.x & 31;
    if (node >= NN) return;
    int beg = g_rowptr[node];
    int dg  = g_deg[node];
    float di = g_dinv[node];
    float nrm2 = di * di;
    const float4* xrow = (const float4*)(x + (size_t)node * 128);
    float4 a = xrow[lane];
    a.x *= nrm2; a.y *= nrm2; a.z *= nrm2; a.w *= nrm2;
    int j = 0;
    for (; j + 3 < dg; j += 4) {
        int   s0 = __ldg(&g_csrc[beg + j + 0]), s1 = __ldg(&g_csrc[beg + j + 1]);
        int   s2 = __ldg(&g_csrc[beg + j + 2]), s3 = __ldg(&g_csrc[beg + j + 3]);
        float n0 = __ldg(&g_cnrm[beg + j + 0]), n1 = __ldg(&g_cnrm[beg + j + 1]);
        float n2 = __ldg(&g_cnrm[beg + j + 2]), n3 = __ldg(&g_cnrm[beg + j + 3]);
        float4 u = ((const float4*)(x + (size_t)s0 * 128))[lane];
        float4 v = ((const float4*)(x + (size_t)s1 * 128))[lane];
        float4 w = ((const float4*)(x + (size_t)s2 * 128))[lane];
        float4 z = ((const float4*)(x + (size_t)s3 * 128))[lane];
        a.x += u.x * n0 + v.x * n1 + w.x * n2 + z.x * n3;
        a.y += u.y * n0 + v.y * n1 + w.y * n2 + z.y * n3;
        a.z += u.z * n0 + v.z * n1 + w.z * n2 + z.z * n3;
        a.w += u.w * n0 + v.w * n1 + w.w * n2 + z.w * n3;
    }
    for (; j < dg; j++) {
        int s = __ldg(&g_csrc[beg + j]);
        float nm = __ldg(&g_cnrm[beg + j]);
        float4 u = ((const float4*)(x + (size_t)s * 128))[lane];
        a.x += u.x * nm; a.y += u.y * nm; a.z += u.z * nm; a.w += u.w * nm;
    }
    uint2 hp, lp;
    split4(a, hp, lp);
    ((uint2*)(g_xhi + (size_t)node * 128))[lane] = hp;
    ((uint2*)(g_xlo + (size_t)node * 128))[lane] = lp;
}

// ---------------- bf16 GEMM, CTA tile 128x256, K-chunk 32, 1 CTA/SM, PDL --------
// mode 0: outH = A@W (f32).  mode 1: g_ahi/g_alo = split(relu(A@W + bias))
// stage: Ahi @0 (128*40*2=10240), Alo @10240, Bhi @20480 (256*40*2), Blo @40960
#define TSTR  40
#define SA_LO 10240
#define SB_H  20480
#define SB_L  40960
#define STG   61440
#define GEMM_SMEM 122880

__global__ void __launch_bounds__(256, 1)
k_gemm(const __nv_bfloat16* __restrict__ ahi, const __nv_bfloat16* __restrict__ alo,
       const __nv_bfloat16* __restrict__ wt_hi, const __nv_bfloat16* __restrict__ wt_lo,
       float* __restrict__ outH, const float* __restrict__ bias, int mode, int M, int K)
{
    extern __shared__ char smem[];
    uint32_t sb = smem_u32(smem);
    int tid = threadIdx.x;
    int wid = tid >> 5;
    int lane = tid & 31;
    int bm = blockIdx.x * 128;
    int wm = (wid >> 2) * 64;    // 2 warp-rows of 64
    int wn = (wid & 3) * 64;     // 4 warp-cols of 64

    const int nch = K >> 5;

    gdc_wait();

    // stage: A = 1024 cp16 (2 splits x 128 rows x 4 groups), B = 2048 cp16
#define STAGE(tt) do {                                                          \
        int k0b = (tt) * 32;                                                    \
        uint32_t base = sb + ((tt) & 1) * STG;                                  \
        _Pragma("unroll")                                                       \
        for (int it = 0; it < 12; it++) {                                       \
            int idx = tid + it * 256;   /* 0..3071 */                           \
            if (idx < 1024) {                                                   \
                int split = idx >> 9;                                           \
                int row = (idx & 511) >> 2, g = idx & 3;                        \
                uint32_t off = (uint32_t)(row * TSTR + g * 8) * 2               \
                             + (split ? SA_LO : 0);                             \
                const __nv_bfloat16* src = (split ? alo : ahi)                  \
                             + (size_t)(bm + row) * K + k0b + g * 8;            \
                cp16(base + off, src);                                          \
            } else {                                                            \
                int idx2 = idx - 1024;                                          \
                int split = idx2 >> 10;                                         \
                int row = (idx2 & 1023) >> 2, g = idx2 & 3;                     \
                uint32_t off = (uint32_t)(row * TSTR + g * 8) * 2               \
                             + (split ? SB_L : SB_H);                           \
                const __nv_bfloat16* src = (split ? wt_lo : wt_hi)              \
                             + (size_t)row * K + k0b + g * 8;                   \
                cp16(base + off, src);                                          \
            }                                                                   \
        }                                                                       \
        CP_COMMIT();                                                            \
    } while (0)

    STAGE(0);

    float acc[4][8][4];
#pragma unroll
    for (int mi = 0; mi < 4; mi++)
#pragma unroll
        for (int ni = 0; ni < 8; ni++)
#pragma unroll
            for (int q = 0; q < 4; q++) acc[mi][ni][q] = 0.0f;

    for (int t = 0; t < nch; t++) {
        if (t + 1 < nch) { STAGE(t + 1); CP_WAIT(1); }
        else             { CP_WAIT(0); }
        __syncthreads();

        uint32_t base = sb + (t & 1) * STG;
#pragma unroll
        for (int ks = 0; ks < 2; ks++) {
            uint32_t ah[4][4], al[4][4], bh[4][4], bl[4][4];
            int arow = (lane & 15);
            int acol = ks * 16 + ((lane >> 4) << 3);
#pragma unroll
            for (int mi = 0; mi < 4; mi++) {
                uint32_t off = (uint32_t)((wm + mi * 16 + arow) * TSTR + acol) * 2;
                ldmat_x4(ah[mi], base + off);
                ldmat_x4(al[mi], base + SA_LO + off);
            }
            int brow = ((lane >> 4) << 3) + (lane & 7);
            int bcol = ks * 16 + ((lane >> 3) & 1) * 8;
#pragma unroll
            for (int j = 0; j < 4; j++) {
                uint32_t off = (uint32_t)((wn + 16 * j + brow) * TSTR + bcol) * 2;
                ldmat_x4(bh[j], base + SB_H + off);
                ldmat_x4(bl[j], base + SB_L + off);
            }
#pragma unroll
            for (int mi = 0; mi < 4; mi++) {
#pragma unroll
                for (int ni = 0; ni < 8; ni++) {
                    const uint32_t* bhp = &bh[ni >> 1][(ni & 1) * 2];
                    const uint32_t* blp = &bl[ni >> 1][(ni & 1) * 2];
                    mma16816(acc[mi][ni], ah[mi], bhp);
                    mma16816(acc[mi][ni], ah[mi], blp);
                    mma16816(acc[mi][ni], al[mi], bhp);
                }
            }
        }
        if (t + 1 < nch) __syncthreads();
    }

    // epilogue: full 128x256 tile
    {
        int g = lane >> 2, tg = lane & 3;
#pragma unroll
        for (int mi = 0; mi < 4; mi++) {
            int r0 = bm + wm + mi * 16 + g;
            int r1 = r0 + 8;
#pragma unroll
            for (int ni = 0; ni < 8; ni++) {
                int col = wn + ni * 8 + tg * 2;
                float* c = acc[mi][ni];
                if (mode == 0) {
                    if (r0 < M) *(float2*)(outH + (size_t)r0 * 256 + col) = make_float2(c[0], c[1]);
                    if (r1 < M) *(float2*)(outH + (size_t)r1 * 256 + col) = make_float2(c[2], c[3]);
                } else {
                    float2 bv = *(const float2*)(bias + col);
                    if (r0 < M) {
                        float v0 = fmaxf(c[0] + bv.x, 0.f), v1 = fmaxf(c[1] + bv.y, 0.f);
                        uint32_t hp, lp;
                        split2(v0, v1, hp, lp);
                        *(uint32_t*)(g_ahi + (size_t)r0 * 256 + col) = hp;
                        *(uint32_t*)(g_alo + (size_t)r0 * 256 + col) = lp;
                    }
                    if (r1 < M) {
                        float v0 = fmaxf(c[2] + bv.x, 0.f), v1 = fmaxf(c[3] + bv.y, 0.f);
                        uint32_t hp, lp;
                        split2(v0, v1, hp, lp);
                        *(uint32_t*)(g_ahi + (size_t)r1 * 256 + col) = hp;
                        *(uint32_t*)(g_alo + (size_t)r1 * 256 + col) = lp;
                    }
                }
            }
        }
    }
    gdc_launch();   // after stores
#undef STAGE
}

// ---------------- CSR gather (4-deep prefetch) -> +bias, relu -> bf16 hi/lo -----
__global__ void __launch_bounds__(256) k_gather(const float* __restrict__ bias) {
    int node = blockIdx.x * 8 + (threadIdx.x >> 5);
    int lane = threadIdx.x & 31;
    if (node >= NN) { gdc_wait(); return; }
    int beg = g_rowptr[node];
    int dg  = g_deg[node];
    float di = g_dinv[node];
    float nrm2 = di * di;
    const float4* bias4 = (const float4*)bias;
    float4 b0 = __ldg(&bias4[lane]);
    float4 b1 = __ldg(&bias4[lane + 32]);
    gdc_wait();
    const float4* hrow = (const float4*)(g_bufH + (size_t)node * FDIM);
    float4 h0 = hrow[lane];
    float4 h1 = hrow[lane + 32];
    float4 a0, a1;
    a0.x = h0.x * nrm2 + b0.x; a0.y = h0.y * nrm2 + b0.y;
    a0.z = h0.z * nrm2 + b0.z; a0.w = h0.w * nrm2 + b0.w;
    a1.x = h1.x * nrm2 + b1.x; a1.y = h1.y * nrm2 + b1.y;
    a1.z = h1.z * nrm2 + b1.z; a1.w = h1.w * nrm2 + b1.w;

    int j = 0;
    for (; j + 3 < dg; j += 4) {
        int   s0 = __ldg(&g_csrc[beg + j + 0]), s1 = __ldg(&g_csrc[beg + j + 1]);
        int   s2 = __ldg(&g_csrc[beg + j + 2]), s3 = __ldg(&g_csrc[beg + j + 3]);
        float n0 = __ldg(&g_cnrm[beg + j + 0]), n1 = __ldg(&g_cnrm[beg + j + 1]);
        float n2 = __ldg(&g_cnrm[beg + j + 2]), n3 = __ldg(&g_cnrm[beg + j + 3]);
        const float4* p0 = (const float4*)(g_bufH + (size_t)s0 * FDIM);
        const float4* p1 = (const float4*)(g_bufH + (size_t)s1 * FDIM);
        const float4* p2 = (const float4*)(g_bufH + (size_t)s2 * FDIM);
        const float4* p3 = (const float4*)(g_bufH + (size_t)s3 * FDIM);
        float4 u0 = p0[lane], u1 = p0[lane + 32];
        float4 v0 = p1[lane], v1 = p1[lane + 32];
        float4 w0 = p2[lane], w1 = p2[lane + 32];
        float4 z0 = p3[lane], z1 = p3[lane + 32];
        a0.x += u0.x * n0; a0.y += u0.y * n0; a0.z += u0.z * n0; a0.w += u0.w * n0;
        a1.x += u1.x * n0; a1.y += u1.y * n0; a1.z += u1.z * n0; a1.w += u1.w * n0;
        a0.x += v0.x * n1; a0.y += v0.y * n1; a0.z += v0.z * n1; a0.w += v0.w * n1;
        a1.x += v1.x * n1; a1.y += v1.y * n1; a1.z += v1.z * n1; a1.w += v1.w * n1;
        a0.x += w0.x * n2; a0.y += w0.y * n2; a0.z += w0.z * n2; a0.w += w0.w * n2;
        a1.x += w1.x * n2; a1.y += w1.y * n2; a1.z += w1.z * n2; a1.w += w1.w * n2;
        a0.x += z0.x * n3; a0.y += z0.y * n3; a0.z += z0.z * n3; a0.w += z0.w * n3;
        a1.x += z1.x * n3; a1.y += z1.y * n3; a1.z += z1.z * n3; a1.w += z1.w * n3;
    }
    for (; j < dg; j++) {
        int s = __ldg(&g_csrc[beg + j]);
        float nm = __ldg(&g_cnrm[beg + j]);
        const float4* p = (const float4*)(g_bufH + (size_t)s * FDIM);
        float4 v0 = p[lane], v1 = p[lane + 32];
        a0.x += v0.x * nm; a0.y += v0.y * nm; a0.z += v0.z * nm; a0.w += v0.w * nm;
        a1.x += v1.x * nm; a1.y += v1.y * nm; a1.z += v1.z * nm; a1.w += v1.w * nm;
    }
    a0.x = fmaxf(a0.x, 0.f); a0.y = fmaxf(a0.y, 0.f);
    a0.z = fmaxf(a0.z, 0.f); a0.w = fmaxf(a0.w, 0.f);
    a1.x = fmaxf(a1.x, 0.f); a1.y = fmaxf(a1.y, 0.f);
    a1.z = fmaxf(a1.z, 0.f); a1.w = fmaxf(a1.w, 0.f);
    uint2 hp0, lp0, hp1, lp1;
    split4(a0, hp0, lp0);
    split4(a1, hp1, lp1);
    uint2* hi = (uint2*)(g_ahi + (size_t)node * FDIM);
    uint2* lo = (uint2*)(g_alo + (size_t)node * FDIM);
    hi[lane]      = hp0;
    hi[lane + 32] = hp1;
    lo[lane]      = lp0;
    lo[lane + 32] = lp1;
    gdc_launch();   // after stores
}

// ---------------- fused pool + FC (PDL, 4-node ILP) ----------------
__device__ __forceinline__ int lbound(const int* a, int n, int key) {
    int lo = 0, hi = n;
    while (lo < hi) { int m = (lo + hi) >> 1; if (a[m] < key) lo = m + 1; else hi = m; }
    return lo;
}

__global__ void k_poolfc(const float* __restrict__ Wfc, const float* __restrict__ bfc,
                         float* __restrict__ out) {
    __shared__ float sp[FDIM];
    __shared__ int bnd[2];
    int g = blockIdx.x;
    int t = threadIdx.x;
    if (t == 0) bnd[0] = lbound(g_batch, NN, g);
    if (t == 1) bnd[1] = lbound(g_batch, NN, g + 1);
    __syncthreads();
    gdc_wait();
    int lo = bnd[0], hi = bnd[1];
    float acc = 0.f;
    int n = lo;
    for (; n + 3 < hi; n += 4) {
        float h0 = __bfloat162float(g_ahi[(size_t)(n + 0) * FDIM + t]);
        float l0 = __bfloat162float(g_alo[(size_t)(n + 0) * FDIM + t]);
        float h1 = __bfloat162float(g_ahi[(size_t)(n + 1) * FDIM + t]);
        float l1 = __bfloat162float(g_alo[(size_t)(n + 1) * FDIM + t]);
        float h2 = __bfloat162float(g_ahi[(size_t)(n + 2) * FDIM + t]);
        float l2 = __bfloat162float(g_alo[(size_t)(n + 2) * FDIM + t]);
        float h3 = __bfloat162float(g_ahi[(size_t)(n + 3) * FDIM + t]);
        float l3 = __bfloat162float(g_alo[(size_t)(n + 3) * FDIM + t]);
        acc += fmaxf(h0 + l0, 0.f) + fmaxf(h1 + l1, 0.f)
             + fmaxf(h2 + l2, 0.f) + fmaxf(h3 + l3, 0.f);
    }
    for (; n < hi; n++) {
        float h0 = __bfloat162float(g_ahi[(size_t)n * FDIM + t]);
        float l0 = __bfloat162float(g_alo[(size_t)n * FDIM + t]);
        acc += fmaxf(h0 + l0, 0.f);
    }
    int cnt = hi - lo;
    sp[t] = cnt > 0 ? acc / (float)cnt : 0.f;
    __syncthreads();
    if (t < FOUT) {
        float o = bfc[t];
#pragma unroll 4
        for (int f = 0; f < FDIM; f++) o += sp[f] * Wfc[(size_t)f * FOUT + t];
        out[(size_t)g * FOUT + t] = o;
    }
}

// ---------------- PDL launch helper ----------------
static void pdl_launch(const void* fn, int grid, int block, size_t smem, void** args) {
    cudaLaunchConfig_t cfg = {};
    cfg.gridDim = dim3((unsigned)grid, 1, 1);
    cfg.blockDim = dim3((unsigned)block, 1, 1);
    cfg.dynamicSmemBytes = smem;
    cfg.stream = 0;
    static cudaLaunchAttribute attr[1];
    attr[0].id = cudaLaunchAttributeProgrammaticStreamSerialization;
    attr[0].val.programmaticStreamSerializationAllowed = 1;
    cfg.attrs = attr;
    cfg.numAttrs = 1;
    cudaLaunchKernelExC(&cfg, fn, args);
}

// ---------------- launch ----------------
extern "C" void kernel_launch(void* const* d_in, const int* in_sizes, int n_in,
                              void* d_out, int out_size) {
    (void)in_sizes; (void)n_in; (void)out_size;
    const float* x   = (const float*)d_in[0];
    const void*  ei  = d_in[1];
    const void*  bt  = d_in[2];
    const float* W1  = (const float*)d_in[3];
    const float* b1  = (const float*)d_in[4];
    const float* W2  = (const float*)d_in[5];
    const float* b2  = (const float*)d_in[6];
    const float* W3  = (const float*)d_in[7];
    const float* b3  = (const float*)d_in[8];
    const float* Wfc = (const float*)d_in[9];
    const float* bfc = (const float*)d_in[10];
    float* out = (float*)d_out;

    float* bufH = nullptr;
    cudaGetSymbolAddress((void**)&bufH, g_bufH);
    __nv_bfloat16 *ahi, *alo, *xhi, *xlo, *w1h, *w1l, *w2h, *w2l, *w3h, *w3l;
    cudaGetSymbolAddress((void**)&ahi, g_ahi);
    cudaGetSymbolAddress((void**)&alo, g_alo);
    cudaGetSymbolAddress((void**)&xhi, g_xhi);
    cudaGetSymbolAddress((void**)&xlo, g_xlo);
    cudaGetSymbolAddress((void**)&w1h, g_w1hi);
    cudaGetSymbolAddress((void**)&w1l, g_w1lo);
    cudaGetSymbolAddress((void**)&w2h, g_w2hi);
    cudaGetSymbolAddress((void**)&w2l, g_w2lo);
    cudaGetSymbolAddress((void**)&w3h, g_w3hi);
    cudaGetSymbolAddress((void**)&w3l, g_w3lo);

    cudaFuncSetAttribute(k_gemm, cudaFuncAttributeMaxDynamicSharedMemorySize, GEMM_SMEM);

    k_zero<<<NBLK, 256>>>();
    k_prep<<<(P_TOTAL + 255) / 256, 256>>>(ei, bt, W1, W2, W3);
    k_scan<<<NBLK, 256>>>();
    k_csrfill<<<(NE + 255) / 256, 256>>>();

    const int gemm_grid = (NN + 127) / 128;   // 782
    const int gat_grid  = (NN + 7) / 8;
    int M = NN;
    int K1 = 128, K2 = 256;
    int mode0 = 0, mode1 = 1;
    const float* nob = nullptr;

    // layer 1: aggregate x (128-dim), then GEMM1 (xhi/xlo -> ahi/alo, fused bias/relu)
    k_gatherx<<<gat_grid, 256>>>(x);
    { void* a[] = { (void*)&xhi, (void*)&xlo, (void*)&w1h, (void*)&w1l, (void*)&bufH,
                    (void*)&b1, (void*)&mode1, (void*)&M, (void*)&K1 };
      pdl_launch((const void*)k_gemm, gemm_grid, 256, GEMM_SMEM, a); }
    // layer 2
    { void* a[] = { (void*)&ahi, (void*)&alo, (void*)&w2h, (void*)&w2l, (void*)&bufH,
                    (void*)&nob, (void*)&mode0, (void*)&M, (void*)&K2 };
      pdl_launch((const void*)k_gemm, gemm_grid, 256, GEMM_SMEM, a); }
    { void* a[] = { (void*)&b2 };
      pdl_launch((const void*)k_gather, gat_grid, 256, 0, a); }
    // layer 3
    { void* a[] = { (void*)&ahi, (void*)&alo, (void*)&w3h, (void*)&w3l, (void*)&bufH,
                    (void*)&nob, (void*)&mode0, (void*)&M, (void*)&K2 };
      pdl_launch((const void*)k_gemm, gemm_grid, 256, GEMM_SMEM, a); }
    { void* a[] = { (void*)&b3 };
      pdl_launch((const void*)k_gather, gat_grid, 256, 0, a); }
    // pool + fc
    { void* a[] = { (void*)&Wfc, (void*)&bfc, (void*)&out };
      pdl_launch((const void*)k_poolfc, NG, FDIM, 0, a); }
}

// round 17
// speedup vs baseline: 1.0779x; 1.0779x over previous
#include <cuda_runtime.h>
#include <cuda_bf16.h>
#include <math.h>
#include <stdint.h>

#define NN 100000
#define NE 320000
#define NG 512
#define FDIM 256
#define FOUT 128
#define NBLK 391   // ceil(NN/256)

// ---------------- scratch (static device memory; no allocation) ----------------
__device__ __align__(16) float g_bufH[(size_t)NN * FDIM];
__device__ __align__(16) __nv_bfloat16 g_ahi[(size_t)(NN + 128) * FDIM];
__device__ __align__(16) __nv_bfloat16 g_alo[(size_t)(NN + 128) * FDIM];
__device__ __align__(16) __nv_bfloat16 g_xhi[(size_t)(NN + 128) * 128];
__device__ __align__(16) __nv_bfloat16 g_xlo[(size_t)(NN + 128) * 128];
__device__ float g_dinv[NN];
__device__ int   g_deg[NN];        // zero-init at load; re-zeroed by k_poolfc
__device__ int   g_rowptr[NN];
__device__ int   g_cursor[NN];
__device__ int   g_state[NBLK];    // zero-init at load; re-zeroed by k_poolfc
__device__ int   g_csrc[NE];
__device__ float g_cnrm[NE];
__device__ int   g_src[NE];
__device__ int   g_dst[NE];
__device__ int   g_batch[NN];
__device__ __align__(16) __nv_bfloat16 g_w1hi[128 * 256];
__device__ __align__(16) __nv_bfloat16 g_w1lo[128 * 256];
__device__ __align__(16) __nv_bfloat16 g_w2hi[256 * 256];
__device__ __align__(16) __nv_bfloat16 g_w2lo[256 * 256];
__device__ __align__(16) __nv_bfloat16 g_w3hi[256 * 256];
__device__ __align__(16) __nv_bfloat16 g_w3lo[256 * 256];

// ---------------- helpers ----------------
__device__ __forceinline__ uint32_t smem_u32(const void* p) {
    uint32_t a;
    asm("{ .reg .u64 t; cvta.to.shared.u64 t, %1; cvt.u32.u64 %0, t; }" : "=r"(a) : "l"(p));
    return a;
}
__device__ __forceinline__ void ldmat_x4(uint32_t* r, uint32_t addr) {
    asm volatile("ldmatrix.sync.aligned.m8n8.x4.shared.b16 {%0,%1,%2,%3}, [%4];"
                 : "=r"(r[0]), "=r"(r[1]), "=r"(r[2]), "=r"(r[3]) : "r"(addr));
}
__device__ __forceinline__ void mma16816(float* c, const uint32_t* a, const uint32_t* b) {
    asm volatile("mma.sync.aligned.m16n8k16.row.col.f32.bf16.bf16.f32 "
                 "{%0,%1,%2,%3}, {%4,%5,%6,%7}, {%8,%9}, {%0,%1,%2,%3};"
                 : "+f"(c[0]), "+f"(c[1]), "+f"(c[2]), "+f"(c[3])
                 : "r"(a[0]), "r"(a[1]), "r"(a[2]), "r"(a[3]), "r"(b[0]), "r"(b[1]));
}
__device__ __forceinline__ void cp16(uint32_t smem_addr, const void* gptr) {
    asm volatile("cp.async.cg.shared.global [%0], [%1], 16;" :: "r"(smem_addr), "l"(gptr));
}
#define CP_COMMIT() asm volatile("cp.async.commit_group;" ::: "memory")
#define CP_WAIT(n)  asm volatile("cp.async.wait_group %0;" :: "n"(n) : "memory")

__device__ __forceinline__ void gdc_wait()   { asm volatile("griddepcontrol.wait;" ::: "memory"); }
__device__ __forceinline__ void gdc_launch() { asm volatile("griddepcontrol.launch_dependents;" ::: "memory"); }

__device__ __forceinline__ void split4(float4 v, uint2& hp, uint2& lp) {
    __nv_bfloat16 h0 = __float2bfloat16(v.x), h1 = __float2bfloat16(v.y);
    __nv_bfloat16 h2 = __float2bfloat16(v.z), h3 = __float2bfloat16(v.w);
    __nv_bfloat16 l0 = __float2bfloat16(v.x - __bfloat162float(h0));
    __nv_bfloat16 l1 = __float2bfloat16(v.y - __bfloat162float(h1));
    __nv_bfloat16 l2 = __float2bfloat16(v.z - __bfloat162float(h2));
    __nv_bfloat16 l3 = __float2bfloat16(v.w - __bfloat162float(h3));
    hp.x = ((uint32_t)__bfloat16_as_ushort(h1) << 16) | __bfloat16_as_ushort(h0);
    hp.y = ((uint32_t)__bfloat16_as_ushort(h3) << 16) | __bfloat16_as_ushort(h2);
    lp.x = ((uint32_t)__bfloat16_as_ushort(l1) << 16) | __bfloat16_as_ushort(l0);
    lp.y = ((uint32_t)__bfloat16_as_ushort(l3) << 16) | __bfloat16_as_ushort(l2);
}
__device__ __forceinline__ void split2(float a, float b, uint32_t& hp, uint32_t& lp) {
    __nv_bfloat16 h0 = __float2bfloat16(a), h1 = __float2bfloat16(b);
    __nv_bfloat16 l0 = __float2bfloat16(a - __bfloat162float(h0));
    __nv_bfloat16 l1 = __float2bfloat16(b - __bfloat162float(h1));
    hp = ((uint32_t)__bfloat16_as_ushort(h1) << 16) | __bfloat16_as_ushort(h0);
    lp = ((uint32_t)__bfloat16_as_ushort(l1) << 16) | __bfloat16_as_ushort(l0);
}

// ---------------- merged prep (edges + batch + weight splits) ----------
#define PW1 (128 * 256)
#define PW2 (256 * 256)
#define P_TOTAL (PW1 + 2 * PW2 + NE + NN)

__global__ void k_prep(const void* e, const void* b,
                       const float* __restrict__ W1,
                       const float* __restrict__ W2, const float* __restrict__ W3) {
    __shared__ int s64;
    if (threadIdx.x == 0) {
        const long long* p = (const long long*)e;
        int is64 = 1;
        for (int t = 0; t < 16; t++) {
            long long v = p[t];
            if (v < 0 || v >= NN) is64 = 0;
        }
        s64 = is64;
    }
    __syncthreads();
    int f64 = s64;
    int i = blockIdx.x * blockDim.x + threadIdx.x;
    if (i < PW1) {
        int k = i >> 8, n = i & 255;
        float v = W1[i];
        __nv_bfloat16 h = __float2bfloat16(v);
        g_w1hi[(size_t)n * 128 + k] = h;
        g_w1lo[(size_t)n * 128 + k] = __float2bfloat16(v - __bfloat162float(h));
        return;
    }
    i -= PW1;
    if (i < PW2) {
        int k = i >> 8, n = i & 255;
        float v = W2[i];
        __nv_bfloat16 h = __float2bfloat16(v);
        g_w2hi[(size_t)n * 256 + k] = h;
        g_w2lo[(size_t)n * 256 + k] = __float2bfloat16(v - __bfloat162float(h));
        return;
    }
    i -= PW2;
    if (i < PW2) {
        int k = i >> 8, n = i & 255;
        float v = W3[i];
        __nv_bfloat16 h = __float2bfloat16(v);
        g_w3hi[(size_t)n * 256 + k] = h;
        g_w3lo[(size_t)n * 256 + k] = __float2bfloat16(v - __bfloat162float(h));
        return;
    }
    i -= PW2;
    if (i < NE) {
        int s, d;
        if (f64) {
            const long long* p = (const long long*)e;
            s = (int)p[i]; d = (int)p[NE + i];
        } else {
            const int* p = (const int*)e;
            s = p[i]; d = p[NE + i];
        }
        g_src[i] = s;
        g_dst[i] = d;
        atomicAdd(&g_deg[d], 1);
        return;
    }
    i -= NE;
    if (i < NN) {
        if (f64) g_batch[i] = (int)((const long long*)b)[i];
        else     g_batch[i] = ((const int*)b)[i];
    }
}

// ---------------- decoupled-lookback scan ----------------
__global__ void k_scan() {
    __shared__ int s[256];
    __shared__ int sprefix;
    int tid = threadIdx.x;
    int blk = blockIdx.x;
    int i = blk * 256 + tid;
    int deg = (i < NN) ? g_deg[i] : 0;
    s[tid] = deg;
#pragma unroll
    for (int off = 1; off < 256; off <<= 1) {
        __syncthreads();
        int t = (tid >= off) ? s[tid - off] : 0;
        __syncthreads();
        s[tid] += t;
    }
    __syncthreads();
    int total = s[255];
    if (tid == 0) {
        if (blk == 0) {
            atomicExch(&g_state[0], (2 << 28) | total);
            sprefix = 0;
        } else {
            atomicExch(&g_state[blk], (1 << 28) | total);
            int run = 0, j = blk - 1;
            while (true) {
                int w = atomicAdd(&g_state[j], 0);
                int f = w >> 28;
                if (f == 0) continue;
                run += (w & 0x0FFFFFFF);
                if (f == 2) break;
                j--;
            }
            atomicExch(&g_state[blk], (2 << 28) | (run + total));
            sprefix = run;
        }
    }
    __syncthreads();
    if (i < NN) {
        g_rowptr[i] = sprefix + s[tid] - deg;
        g_cursor[i] = 0;
        g_dinv[i] = rsqrtf((float)deg + 1.0f);
    }
}

__global__ void k_csrfill() {
    int e = blockIdx.x * blockDim.x + threadIdx.x;
    if (e >= NE) return;
    int s = g_src[e], d = g_dst[e];
    int pos = atomicAdd(&g_cursor[d], 1);
    int slot = g_rowptr[d] + pos;
    g_csrc[slot] = s;
    g_cnrm[slot] = g_dinv[s] * g_dinv[d];
}

// ---------------- layer-1 pre-aggregation: xagg = A_norm @ x (128-dim) ----------
__global__ void __launch_bounds__(256) k_gatherx(const float* __restrict__ x) {
    int node = blockIdx.x * 8 + (threadIdx.x >> 5);
    int lane = threadIdx.x & 31;
    if (node >= NN) return;
    int beg = g_rowptr[node];
    int dg  = g_deg[node];
    float di = g_dinv[node];
    float nrm2 = di * di;
    const float4* xrow = (const float4*)(x + (size_t)node * 128);
    float4 a = xrow[lane];
    a.x *= nrm2; a.y *= nrm2; a.z *= nrm2; a.w *= nrm2;
    int j = 0;
    for (; j + 3 < dg; j += 4) {
        int   s0 = __ldg(&g_csrc[beg + j + 0]), s1 = __ldg(&g_csrc[beg + j + 1]);
        int   s2 = __ldg(&g_csrc[beg + j + 2]), s3 = __ldg(&g_csrc[beg + j + 3]);
        float n0 = __ldg(&g_cnrm[beg + j + 0]), n1 = __ldg(&g_cnrm[beg + j + 1]);
        float n2 = __ldg(&g_cnrm[beg + j + 2]), n3 = __ldg(&g_cnrm[beg + j + 3]);
        float4 u = ((const float4*)(x + (size_t)s0 * 128))[lane];
        float4 v = ((const float4*)(x + (size_t)s1 * 128))[lane];
        float4 w = ((const float4*)(x + (size_t)s2 * 128))[lane];
        float4 z = ((const float4*)(x + (size_t)s3 * 128))[lane];
        a.x += u.x * n0 + v.x * n1 + w.x * n2 + z.x * n3;
        a.y += u.y * n0 + v.y * n1 + w.y * n2 + z.y * n3;
        a.z += u.z * n0 + v.z * n1 + w.z * n2 + z.z * n3;
        a.w += u.w * n0 + v.w * n1 + w.w * n2 + z.w * n3;
    }
    for (; j < dg; j++) {
        int s = __ldg(&g_csrc[beg + j]);
        float nm = __ldg(&g_cnrm[beg + j]);
        float4 u = ((const float4*)(x + (size_t)s * 128))[lane];
        a.x += u.x * nm; a.y += u.y * nm; a.z += u.z * nm; a.w += u.w * nm;
    }
    uint2 hp, lp;
    split4(a, hp, lp);
    ((uint2*)(g_xhi + (size_t)node * 128))[lane] = hp;
    ((uint2*)(g_xlo + (size_t)node * 128))[lane] = lp;
}

// ---------------- bf16 GEMM, CTA tile 64x256, K-chunk 32, 2 CTA/SM, PDL ---------
// mode 0: outH = A@W (f32).  mode 1: g_ahi/g_alo = split(relu(A@W + bias))
#define TSTR  40
#define SA_LO 5120
#define SB_H  10240
#define SB_L  30720
#define STG   51200
#define GEMM_SMEM 102400

__global__ void __launch_bounds__(256, 2)
k_gemm(const __nv_bfloat16* __restrict__ ahi, const __nv_bfloat16* __restrict__ alo,
       const __nv_bfloat16* __restrict__ wt_hi, const __nv_bfloat16* __restrict__ wt_lo,
       float* __restrict__ outH, const float* __restrict__ bias, int mode, int M, int K)
{
    extern __shared__ char smem[];
    uint32_t sb = smem_u32(smem);
    int tid = threadIdx.x;
    int wid = tid >> 5;
    int lane = tid & 31;
    int bm = blockIdx.x * 64;
    int wm = (wid >> 2) * 32;
    int wn = (wid & 3) * 64;

    const int nch = K >> 5;

    gdc_wait();

#define STAGE(tt) do {                                                          \
        int k0b = (tt) * 32;                                                    \
        uint32_t base = sb + ((tt) & 1) * STG;                                  \
        _Pragma("unroll")                                                       \
        for (int it = 0; it < 10; it++) {                                       \
            int idx = tid + it * 256;                                           \
            if (idx < 512) {                                                    \
                int split = idx >> 8;                                           \
                int row = (idx & 255) >> 2, g = idx & 3;                        \
                uint32_t off = (uint32_t)(row * TSTR + g * 8) * 2               \
                             + (split ? SA_LO : 0);                             \
                const __nv_bfloat16* src = (split ? alo : ahi)                  \
                             + (size_t)(bm + row) * K + k0b + g * 8;            \
                cp16(base + off, src);                                          \
            } else {                                                            \
                int idx2 = idx - 512;                                           \
                int split = idx2 >> 10;                                         \
                int row = (idx2 & 1023) >> 2, g = idx2 & 3;                     \
                uint32_t off = (uint32_t)(row * TSTR + g * 8) * 2               \
                             + (split ? SB_L : SB_H);                           \
                const __nv_bfloat16* src = (split ? wt_lo : wt_hi)              \
                             + (size_t)row * K + k0b + g * 8;                   \
                cp16(base + off, src);                                          \
            }                                                                   \
        }                                                                       \
        CP_COMMIT();                                                            \
    } while (0)

    STAGE(0);

    float acc[2][8][4];
#pragma unroll
    for (int mi = 0; mi < 2; mi++)
#pragma unroll
        for (int ni = 0; ni < 8; ni++)
#pragma unroll
            for (int q = 0; q < 4; q++) acc[mi][ni][q] = 0.0f;

    for (int t = 0; t < nch; t++) {
        if (t + 1 < nch) { STAGE(t + 1); CP_WAIT(1); }
        else             { CP_WAIT(0); }
        __syncthreads();

        uint32_t base = sb + (t & 1) * STG;
#pragma unroll
        for (int ks = 0; ks < 2; ks++) {
            uint32_t ah[2][4], al[2][4], bh[4][4], bl[4][4];
            int arow = (lane & 15);
            int acol = ks * 16 + ((lane >> 4) << 3);
#pragma unroll
            for (int mi = 0; mi < 2; mi++) {
                uint32_t off = (uint32_t)((wm + mi * 16 + arow) * TSTR + acol) * 2;
                ldmat_x4(ah[mi], base + off);
                ldmat_x4(al[mi], base + SA_LO + off);
            }
            int brow = ((lane >> 4) << 3) + (lane & 7);
            int bcol = ks * 16 + ((lane >> 3) & 1) * 8;
#pragma unroll
            for (int j = 0; j < 4; j++) {
                uint32_t off = (uint32_t)((wn + 16 * j + brow) * TSTR + bcol) * 2;
                ldmat_x4(bh[j], base + SB_H + off);
                ldmat_x4(bl[j], base + SB_L + off);
            }
#pragma unroll
            for (int mi = 0; mi < 2; mi++) {
#pragma unroll
                for (int ni = 0; ni < 8; ni++) {
                    const uint32_t* bhp = &bh[ni >> 1][(ni & 1) * 2];
                    const uint32_t* blp = &bl[ni >> 1][(ni & 1) * 2];
                    mma16816(acc[mi][ni], ah[mi], bhp);
                    mma16816(acc[mi][ni], ah[mi], blp);
                    mma16816(acc[mi][ni], al[mi], bhp);
                }
            }
        }
        if (t + 1 < nch) __syncthreads();
    }

    // epilogue
    {
        int g = lane >> 2, tg = lane & 3;
#pragma unroll
        for (int mi = 0; mi < 2; mi++) {
            int r0 = bm + wm + mi * 16 + g;
            int r1 = r0 + 8;
#pragma unroll
            for (int ni = 0; ni < 8; ni++) {
                int col = wn + ni * 8 + tg * 2;
                float* c = acc[mi][ni];
                if (mode == 0) {
                    if (r0 < M) *(float2*)(outH + (size_t)r0 * 256 + col) = make_float2(c[0], c[1]);
                    if (r1 < M) *(float2*)(outH + (size_t)r1 * 256 + col) = make_float2(c[2], c[3]);
                } else {
                    float2 bv = *(const float2*)(bias + col);
                    if (r0 < M) {
                        float v0 = fmaxf(c[0] + bv.x, 0.f), v1 = fmaxf(c[1] + bv.y, 0.f);
                        uint32_t hp, lp;
                        split2(v0, v1, hp, lp);
                        *(uint32_t*)(g_ahi + (size_t)r0 * 256 + col) = hp;
                        *(uint32_t*)(g_alo + (size_t)r0 * 256 + col) = lp;
                    }
                    if (r1 < M) {
                        float v0 = fmaxf(c[2] + bv.x, 0.f), v1 = fmaxf(c[3] + bv.y, 0.f);
                        uint32_t hp, lp;
                        split2(v0, v1, hp, lp);
                        *(uint32_t*)(g_ahi + (size_t)r1 * 256 + col) = hp;
                        *(uint32_t*)(g_alo + (size_t)r1 * 256 + col) = lp;
                    }
                }
            }
        }
    }
    gdc_launch();   // after stores
#undef STAGE
}

// ---------------- CSR gather (4-deep prefetch) -> +bias, relu -> bf16 hi/lo -----
__global__ void __launch_bounds__(256) k_gather(const float* __restrict__ bias) {
    int node = blockIdx.x * 8 + (threadIdx.x >> 5);
    int lane = threadIdx.x & 31;
    if (node >= NN) { gdc_wait(); return; }
    int beg = g_rowptr[node];
    int dg  = g_deg[node];
    float di = g_dinv[node];
    float nrm2 = di * di;
    const float4* bias4 = (const float4*)bias;
    float4 b0 = __ldg(&bias4[lane]);
    float4 b1 = __ldg(&bias4[lane + 32]);
    gdc_wait();
    const float4* hrow = (const float4*)(g_bufH + (size_t)node * FDIM);
    float4 h0 = hrow[lane];
    float4 h1 = hrow[lane + 32];
    float4 a0, a1;
    a0.x = h0.x * nrm2 + b0.x; a0.y = h0.y * nrm2 + b0.y;
    a0.z = h0.z * nrm2 + b0.z; a0.w = h0.w * nrm2 + b0.w;
    a1.x = h1.x * nrm2 + b1.x; a1.y = h1.y * nrm2 + b1.y;
    a1.z = h1.z * nrm2 + b1.z; a1.w = h1.w * nrm2 + b1.w;

    int j = 0;
    for (; j + 3 < dg; j += 4) {
        int   s0 = __ldg(&g_csrc[beg + j + 0]), s1 = __ldg(&g_csrc[beg + j + 1]);
        int   s2 = __ldg(&g_csrc[beg + j + 2]), s3 = __ldg(&g_csrc[beg + j + 3]);
        float n0 = __ldg(&g_cnrm[beg + j + 0]), n1 = __ldg(&g_cnrm[beg + j + 1]);
        float n2 = __ldg(&g_cnrm[beg + j + 2]), n3 = __ldg(&g_cnrm[beg + j + 3]);
        const float4* p0 = (const float4*)(g_bufH + (size_t)s0 * FDIM);
        const float4* p1 = (const float4*)(g_bufH + (size_t)s1 * FDIM);
        const float4* p2 = (const float4*)(g_bufH + (size_t)s2 * FDIM);
        const float4* p3 = (const float4*)(g_bufH + (size_t)s3 * FDIM);
        float4 u0 = p0[lane], u1 = p0[lane + 32];
        float4 v0 = p1[lane], v1 = p1[lane + 32];
        float4 w0 = p2[lane], w1 = p2[lane + 32];
        float4 z0 = p3[lane], z1 = p3[lane + 32];
        a0.x += u0.x * n0; a0.y += u0.y * n0; a0.z += u0.z * n0; a0.w += u0.w * n0;
        a1.x += u1.x * n0; a1.y += u1.y * n0; a1.z += u1.z * n0; a1.w += u1.w * n0;
        a0.x += v0.x * n1; a0.y += v0.y * n1; a0.z += v0.z * n1; a0.w += v0.w * n1;
        a1.x += v1.x * n1; a1.y += v1.y * n1; a1.z += v1.z * n1; a1.w += v1.w * n1;
        a0.x += w0.x * n2; a0.y += w0.y * n2; a0.z += w0.z * n2; a0.w += w0.w * n2;
        a1.x += w1.x * n2; a1.y += w1.y * n2; a1.z += w1.z * n2; a1.w += w1.w * n2;
        a0.x += z0.x * n3; a0.y += z0.y * n3; a0.z += z0.z * n3; a0.w += z0.w * n3;
        a1.x += z1.x * n3; a1.y += z1.y * n3; a1.z += z1.z * n3; a1.w += z1.w * n3;
    }
    for (; j < dg; j++) {
        int s = __ldg(&g_csrc[beg + j]);
        float nm = __ldg(&g_cnrm[beg + j]);
        const float4* p = (const float4*)(g_bufH + (size_t)s * FDIM);
        float4 v0 = p[lane], v1 = p[lane + 32];
        a0.x += v0.x * nm; a0.y += v0.y * nm; a0.z += v0.z * nm; a0.w += v0.w * nm;
        a1.x += v1.x * nm; a1.y += v1.y * nm; a1.z += v1.z * nm; a1.w += v1.w * nm;
    }
    a0.x = fmaxf(a0.x, 0.f); a0.y = fmaxf(a0.y, 0.f);
    a0.z = fmaxf(a0.z, 0.f); a0.w = fmaxf(a0.w, 0.f);
    a1.x = fmaxf(a1.x, 0.f); a1.y = fmaxf(a1.y, 0.f);
    a1.z = fmaxf(a1.z, 0.f); a1.w = fmaxf(a1.w, 0.f);
    uint2 hp0, lp0, hp1, lp1;
    split4(a0, hp0, lp0);
    split4(a1, hp1, lp1);
    uint2* hi = (uint2*)(g_ahi + (size_t)node * FDIM);
    uint2* lo = (uint2*)(g_alo + (size_t)node * FDIM);
    hi[lane]      = hp0;
    hi[lane + 32] = hp1;
    lo[lane]      = lp0;
    lo[lane + 32] = lp1;
    gdc_launch();   // after stores
}

// ---------------- fused pool + FC (PDL, 4-node ILP) + next-run zeroing ----------
__device__ __forceinline__ int lbound(const int* a, int n, int key) {
    int lo = 0, hi = n;
    while (lo < hi) { int m = (lo + hi) >> 1; if (a[m] < key) lo = m + 1; else hi = m; }
    return lo;
}

__global__ void k_poolfc(const float* __restrict__ Wfc, const float* __restrict__ bfc,
                         float* __restrict__ out) {
    __shared__ float sp[FDIM];
    __shared__ int bnd[2];
    int g = blockIdx.x;
    int t = threadIdx.x;
    if (t == 0) bnd[0] = lbound(g_batch, NN, g);
    if (t == 1) bnd[1] = lbound(g_batch, NN, g + 1);
    __syncthreads();
    gdc_wait();
    int lo = bnd[0], hi = bnd[1];
    float acc = 0.f;
    int n = lo;
    for (; n + 3 < hi; n += 4) {
        float h0 = __bfloat162float(g_ahi[(size_t)(n + 0) * FDIM + t]);
        float l0 = __bfloat162float(g_alo[(size_t)(n + 0) * FDIM + t]);
        float h1 = __bfloat162float(g_ahi[(size_t)(n + 1) * FDIM + t]);
        float l1 = __bfloat162float(g_alo[(size_t)(n + 1) * FDIM + t]);
        float h2 = __bfloat162float(g_ahi[(size_t)(n + 2) * FDIM + t]);
        float l2 = __bfloat162float(g_alo[(size_t)(n + 2) * FDIM + t]);
        float h3 = __bfloat162float(g_ahi[(size_t)(n + 3) * FDIM + t]);
        float l3 = __bfloat162float(g_alo[(size_t)(n + 3) * FDIM + t]);
        acc += fmaxf(h0 + l0, 0.f) + fmaxf(h1 + l1, 0.f)
             + fmaxf(h2 + l2, 0.f) + fmaxf(h3 + l3, 0.f);
    }
    for (; n < hi; n++) {
        float h0 = __bfloat162float(g_ahi[(size_t)n * FDIM + t]);
        float l0 = __bfloat162float(g_alo[(size_t)n * FDIM + t]);
        acc += fmaxf(h0 + l0, 0.f);
    }
    int cnt = hi - lo;
    sp[t] = cnt > 0 ? acc / (float)cnt : 0.f;
    __syncthreads();
    if (t < FOUT) {
        float o = bfc[t];
#pragma unroll 4
        for (int f = 0; f < FDIM; f++) o += sp[f] * Wfc[(size_t)f * FOUT + t];
        out[(size_t)g * FOUT + t] = o;
    }
    // re-zero degree + scan state for the NEXT invocation (replaces k_zero launch)
    int gi = g * 256 + t;           // 512*256 = 131072 >= NN, NBLK
    if (gi < NN) g_deg[gi] = 0;
    if (gi < NBLK) g_state[gi] = 0;
}

// ---------------- PDL launch helper ----------------
static void pdl_launch(const void* fn, int grid, int block, size_t smem, void** args) {
    cudaLaunchConfig_t cfg = {};
    cfg.gridDim = dim3((unsigned)grid, 1, 1);
    cfg.blockDim = dim3((unsigned)block, 1, 1);
    cfg.dynamicSmemBytes = smem;
    cfg.stream = 0;
    static cudaLaunchAttribute attr[1];
    attr[0].id = cudaLaunchAttributeProgrammaticStreamSerialization;
    attr[0].val.programmaticStreamSerializationAllowed = 1;
    cfg.attrs = attr;
    cfg.numAttrs = 1;
    cudaLaunchKernelExC(&cfg, fn, args);
}

// ---------------- launch ----------------
extern "C" void kernel_launch(void* const* d_in, const int* in_sizes, int n_in,
                              void* d_out, int out_size) {
    (void)in_sizes; (void)n_in; (void)out_size;
    const float* x   = (const float*)d_in[0];
    const void*  ei  = d_in[1];
    const void*  bt  = d_in[2];
    const float* W1  = (const float*)d_in[3];
    const float* b1  = (const float*)d_in[4];
    const float* W2  = (const float*)d_in[5];
    const float* b2  = (const float*)d_in[6];
    const float* W3  = (const float*)d_in[7];
    const float* b3  = (const float*)d_in[8];
    const float* Wfc = (const float*)d_in[9];
    const float* bfc = (const float*)d_in[10];
    float* out = (float*)d_out;

    float* bufH = nullptr;
    cudaGetSymbolAddress((void**)&bufH, g_bufH);
    __nv_bfloat16 *ahi, *alo, *xhi, *xlo, *w1h, *w1l, *w2h, *w2l, *w3h, *w3l;
    cudaGetSymbolAddress((void**)&ahi, g_ahi);
    cudaGetSymbolAddress((void**)&alo, g_alo);
    cudaGetSymbolAddress((void**)&xhi, g_xhi);
    cudaGetSymbolAddress((void**)&xlo, g_xlo);
    cudaGetSymbolAddress((void**)&w1h, g_w1hi);
    cudaGetSymbolAddress((void**)&w1l, g_w1lo);
    cudaGetSymbolAddress((void**)&w2h, g_w2hi);
    cudaGetSymbolAddress((void**)&w2l, g_w2lo);
    cudaGetSymbolAddress((void**)&w3h, g_w3hi);
    cudaGetSymbolAddress((void**)&w3l, g_w3lo);

    cudaFuncSetAttribute(k_gemm, cudaFuncAttributeMaxDynamicSharedMemorySize, GEMM_SMEM);

    k_prep<<<(P_TOTAL + 255) / 256, 256>>>(ei, bt, W1, W2, W3);
    k_scan<<<NBLK, 256>>>();
    k_csrfill<<<(NE + 255) / 256, 256>>>();

    const int gemm_grid = (NN + 63) / 64;   // 1563
    const int gat_grid  = (NN + 7) / 8;
    int M = NN;
    int K1 = 128, K2 = 256;
    int mode0 = 0, mode1 = 1;
    const float* nob = nullptr;

    // layer 1: aggregate x (128-dim), then GEMM1 (xhi/xlo -> ahi/alo, fused bias/relu)
    k_gatherx<<<gat_grid, 256>>>(x);
    { void* a[] = { (void*)&xhi, (void*)&xlo, (void*)&w1h, (void*)&w1l, (void*)&bufH,
                    (void*)&b1, (void*)&mode1, (void*)&M, (void*)&K1 };
      pdl_launch((const void*)k_gemm, gemm_grid, 256, GEMM_SMEM, a); }
    // layer 2
    { void* a[] = { (void*)&ahi, (void*)&alo, (void*)&w2h, (void*)&w2l, (void*)&bufH,
                    (void*)&nob, (void*)&mode0, (void*)&M, (void*)&K2 };
      pdl_launch((const void*)k_gemm, gemm_grid, 256, GEMM_SMEM, a); }
    { void* a[] = { (void*)&b2 };
      pdl_launch((const void*)k_gather, gat_grid, 256, 0, a); }
    // layer 3
    { void* a[] = { (void*)&ahi, (void*)&alo, (void*)&w3h, (void*)&w3l, (void*)&bufH,
                    (void*)&nob, (void*)&mode0, (void*)&M, (void*)&K2 };
      pdl_launch((const void*)k_gemm, gemm_grid, 256, GEMM_SMEM, a); }
    { void* a[] = { (void*)&b3 };
      pdl_launch((const void*)k_gather, gat_grid, 256, 0, a); }
    // pool + fc
    { void* a[] = { (void*)&Wfc, (void*)&bfc, (void*)&out };
      pdl_launch((const void*)k_poolfc, NG, FDIM, 0, a); }
}